// round 4
// baseline (speedup 1.0000x reference)
#include <cuda_runtime.h>
#include <math.h>

#define FULL 0xFFFFFFFFu
typedef unsigned long long ull;

static const int NB = 16, NN = 4096, NS = 1024, NK = 32, ND = 64;
static const int C0 = 67, C1 = 64, C2 = 64, C3 = 128;

// ---------------- scratch (static device globals; no allocs) ----------------
__device__ int   g_ball[NB * NS * NK];          // 2 MB neighbor indices
__device__ float gW0[C0 * C1], gB0[C1];
__device__ float gW1[C1 * C2], gB1[C2];
__device__ float gW2[C2 * C3], gB2[C3];

// exact (non-contracted) squared distance to match reference mul/add semantics
__device__ __forceinline__ float sq3(float ax, float ay, float az,
                                     float bx, float by, float bz) {
    float dx = __fsub_rn(ax, bx), dy = __fsub_rn(ay, by), dz = __fsub_rn(az, bz);
    return __fadd_rn(__fadd_rn(__fmul_rn(dx, dx), __fmul_rn(dy, dy)), __fmul_rn(dz, dz));
}

__device__ __forceinline__ float bn_scale(float g, float v) {
    return (float)((double)g / sqrt((double)v + 1e-5));
}

// ---------------- kernel 0: fold BN into weights ----------------
__global__ void k_fold(const float* W0, const float* b0, const float* g0, const float* be0, const float* m0, const float* v0,
                       const float* W1, const float* b1, const float* g1, const float* be1, const float* m1, const float* v1,
                       const float* W2, const float* b2, const float* g2, const float* be2, const float* m2, const float* v2) {
    int t = blockIdx.x * blockDim.x + threadIdx.x;
    int st = gridDim.x * blockDim.x;
    for (int i = t; i < C0 * C1; i += st) { int j = i % C1; gW0[i] = W0[i] * bn_scale(g0[j], v0[j]); }
    for (int i = t; i < C1 * C2; i += st) { int j = i % C2; gW1[i] = W1[i] * bn_scale(g1[j], v1[j]); }
    for (int i = t; i < C2 * C3; i += st) { int j = i % C3; gW2[i] = W2[i] * bn_scale(g2[j], v2[j]); }
    for (int j = t; j < C1; j += st) gB0[j] = (b0[j] - m0[j]) * bn_scale(g0[j], v0[j]) + be0[j];
    for (int j = t; j < C2; j += st) gB1[j] = (b1[j] - m1[j]) * bn_scale(g1[j], v1[j]) + be1[j];
    for (int j = t; j < C3; j += st) gB2[j] = (b2[j] - m2[j]) * bn_scale(g2[j], v2[j]) + be2[j];
}

// ---------------- kernel 1: farthest point sampling ----------------
// one block per batch; emits new_xyz directly into d_out[0 : B*S*3]
__global__ void __launch_bounds__(1024) k_fps(const float* __restrict__ xyz, float* __restrict__ out) {
    extern __shared__ float sm[];
    float* sx = sm;
    float* sy = sm + NN;
    float* sz = sm + 2 * NN;
    float* rv = sm + 3 * NN;        // 32 floats
    int*   ri = (int*)(rv + 32);    // 32 ints
    float* scent = (float*)(ri + 32); // 3 floats

    int b = blockIdx.x, t = threadIdx.x;
    const float* xb = xyz + (size_t)b * NN * 3;
    for (int j = t; j < NN; j += 1024) {
        sx[j] = xb[3 * j]; sy[j] = xb[3 * j + 1]; sz[j] = xb[3 * j + 2];
    }
    __syncthreads();
    if (t == 0) {
        scent[0] = sx[0]; scent[1] = sy[0]; scent[2] = sz[0];
        float* o = out + (size_t)b * NS * 3;
        o[0] = sx[0]; o[1] = sy[0]; o[2] = sz[0];
    }
    __syncthreads();

    float md0 = 1e10f, md1 = 1e10f, md2 = 1e10f, md3 = 1e10f;
    const int p0 = t, p1 = t + 1024, p2 = t + 2048, p3 = t + 3072;
    int lane = t & 31, w = t >> 5;

    for (int it = 1; it < NS; it++) {
        float cx = scent[0], cy = scent[1], cz = scent[2];
        md0 = fminf(md0, sq3(sx[p0], sy[p0], sz[p0], cx, cy, cz));
        md1 = fminf(md1, sq3(sx[p1], sy[p1], sz[p1], cx, cy, cz));
        md2 = fminf(md2, sq3(sx[p2], sy[p2], sz[p2], cx, cy, cz));
        md3 = fminf(md3, sq3(sx[p3], sy[p3], sz[p3], cx, cy, cz));
        float bv = md0; int bi = p0;
        if (md1 > bv) { bv = md1; bi = p1; }
        if (md2 > bv) { bv = md2; bi = p2; }
        if (md3 > bv) { bv = md3; bi = p3; }
        #pragma unroll
        for (int off = 16; off; off >>= 1) {
            float ov = __shfl_down_sync(FULL, bv, off);
            int   oi = __shfl_down_sync(FULL, bi, off);
            if (ov > bv || (ov == bv && oi < bi)) { bv = ov; bi = oi; }
        }
        if (lane == 0) { rv[w] = bv; ri[w] = bi; }
        __syncthreads();
        if (t < 32) {
            bv = rv[t]; bi = ri[t];
            #pragma unroll
            for (int off = 16; off; off >>= 1) {
                float ov = __shfl_down_sync(FULL, bv, off);
                int   oi = __shfl_down_sync(FULL, bi, off);
                if (ov > bv || (ov == bv && oi < bi)) { bv = ov; bi = oi; }
            }
            if (t == 0) {
                scent[0] = sx[bi]; scent[1] = sy[bi]; scent[2] = sz[bi];
                float* o = out + ((size_t)b * NS + it) * 3;
                o[0] = sx[bi]; o[1] = sy[bi]; o[2] = sz[bi];
            }
        }
        __syncthreads();
    }
}

// ---------------- kernel 2: ball query (first K in index order) ----------------
__global__ void __launch_bounds__(256) k_ball(const float* __restrict__ xyz, const float* __restrict__ nxyz) {
    extern __shared__ float sm[];
    float* sx = sm; float* sy = sm + NN; float* sz = sm + 2 * NN;
    int b  = blockIdx.x >> 7;          // 128 blocks per batch
    int s0 = (blockIdx.x & 127) << 3;  // 8 centroids per block (one per warp)
    const float* xb = xyz + (size_t)b * NN * 3;
    for (int j = threadIdx.x; j < NN; j += 256) {
        sx[j] = xb[3 * j]; sy[j] = xb[3 * j + 1]; sz[j] = xb[3 * j + 2];
    }
    __syncthreads();
    int w = threadIdx.x >> 5, lane = threadIdx.x & 31;
    int s = s0 + w;
    const float* c = nxyz + ((size_t)b * NS + s) * 3;
    float cx = c[0], cy = c[1], cz = c[2];
    const float R2 = (float)(0.2 * 0.2);  // matches python double 0.04 -> f32 cast
    int gb = ((b << 10) + s) * NK;
    int cnt = 0;
    for (int base = 0; base < NN; base += 32) {
        int p = base + lane;
        float d2 = sq3(cx, cy, cz, sx[p], sy[p], sz[p]);
        bool hit = d2 < R2;
        unsigned m = __ballot_sync(FULL, hit);
        int pos = cnt + __popc(m & ((1u << lane) - 1));
        if (hit && pos < NK) g_ball[gb + pos] = p;
        cnt += __popc(m);
        if (cnt >= NK) break;
    }
    int cf = cnt < NK ? cnt : NK;
    if (lane >= cf) g_ball[gb + lane] = -1;
}

// ---------------- packed f32x2 helpers ----------------
__device__ __forceinline__ void ffma2(ull& acc, ull a, ull b) {
    asm("fma.rn.f32x2 %0, %1, %2, %0;" : "+l"(acc) : "l"(a), "l"(b));
}
__device__ __forceinline__ ull bcast2(float x) {
    ull r; asm("mov.b64 %0, {%1, %1};" : "=l"(r) : "f"(x)); return r;
}
__device__ __forceinline__ ull pk2(float a, float b) {
    ull r; asm("mov.b64 %0, {%1, %2};" : "=l"(r) : "f"(a), "f"(b)); return r;
}
__device__ __forceinline__ void unpk(ull v, float& a, float& b) {
    asm("mov.b64 {%0, %1}, %2;" : "=f"(a), "=f"(b) : "l"(v));
}
// accumulate xv * W[c][0..63] into h[0..31] (packed pairs)
__device__ __forceinline__ void chan64(float xv, const float* wrow, ull* h) {
    ull x2 = bcast2(xv);
    const ulonglong2* w2 = (const ulonglong2*)wrow;
    #pragma unroll
    for (int j = 0; j < 16; j++) {
        ulonglong2 w = w2[j];
        ffma2(h[2 * j],     x2, w.x);
        ffma2(h[2 * j + 1], x2, w.y);
    }
}

// ---------------- kernel 3: gather + 3-layer MLP + max over K ----------------
// one warp per centroid, lane = neighbor k; 8 warps/block, 2 centroids/warp
__global__ void __launch_bounds__(256) k_mlp(const float* __restrict__ xyz,
                                             const float* __restrict__ points,
                                             const float* __restrict__ nxyz,
                                             float* __restrict__ out_pts) {
    extern __shared__ float sm[];
    float* sW0 = sm;                 // 4288
    float* sW1 = sW0 + C0 * C1;      // 4096
    float* sW2 = sW1 + C1 * C2;      // 8192
    float* sB0 = sW2 + C2 * C3;      // 64
    float* sB1 = sB0 + C1;           // 64
    float* sB2 = sB1 + C2;           // 128
    float* sAct = sB2 + C3;          // 8 warps * 32 lanes * 65 (padded)

    for (int i = threadIdx.x; i < C0 * C1; i += 256) sW0[i] = gW0[i];
    for (int i = threadIdx.x; i < C1 * C2; i += 256) sW1[i] = gW1[i];
    for (int i = threadIdx.x; i < C2 * C3; i += 256) sW2[i] = gW2[i];
    if (threadIdx.x < C1) sB0[threadIdx.x] = gB0[threadIdx.x];
    if (threadIdx.x < C2) sB1[threadIdx.x] = gB1[threadIdx.x];
    if (threadIdx.x < C3) sB2[threadIdx.x] = gB2[threadIdx.x];
    __syncthreads();

    int w = threadIdx.x >> 5, lane = threadIdx.x & 31;
    float* act = sAct + w * (32 * 65) + lane * 65;  // private per-lane row, conflict-free

    #pragma unroll 1
    for (int r = 0; r < 2; r++) {
        int cid = blockIdx.x * 16 + r * 8 + w;
        int b = cid >> 10;
        const float* cen = nxyz + (size_t)cid * 3;
        float cx = cen[0], cy = cen[1], cz = cen[2];

        int nidx = g_ball[cid * NK + lane];
        int iw = nidx < 0 ? (NN - 1) : nidx;   // torch -1 wrap -> N-1
        const float4* prow = (const float4*)(points + ((size_t)b * NN + iw) * ND);

        float x0, x1, x2v;
        if (nidx >= 0) {
            const float* q = xyz + ((size_t)b * NN + nidx) * 3;
            x0 = __fsub_rn(q[0], cx); x1 = __fsub_rn(q[1], cy); x2v = __fsub_rn(q[2], cz);
        } else {
            // padded slot: grouped_xyz was zeroed BEFORE the -new_xyz subtraction
            x0 = -cx; x1 = -cy; x2v = -cz;
        }

        // ---- layer 1: 67 -> 64 ----
        ull h[32];
        {
            const ull* bb = (const ull*)sB0;
            #pragma unroll
            for (int q = 0; q < 32; q++) h[q] = bb[q];
        }
        chan64(x0,  sW0,        h);
        chan64(x1,  sW0 + 64,   h);
        chan64(x2v, sW0 + 128,  h);
        float4 cur = prow[0];
        #pragma unroll 1
        for (int i = 0; i < 16; i++) {
            float4 nxt = (i < 15) ? prow[i + 1] : cur;
            const float* wr = sW0 + (3 + 4 * i) * 64;
            chan64(cur.x, wr,       h);
            chan64(cur.y, wr + 64,  h);
            chan64(cur.z, wr + 128, h);
            chan64(cur.w, wr + 192, h);
            cur = nxt;
        }
        #pragma unroll
        for (int q = 0; q < 32; q++) {
            float a, bb2; unpk(h[q], a, bb2);
            act[2 * q] = fmaxf(a, 0.f); act[2 * q + 1] = fmaxf(bb2, 0.f);
        }

        // ---- layer 2: 64 -> 64 ----
        {
            const ull* bb = (const ull*)sB1;
            #pragma unroll
            for (int q = 0; q < 32; q++) h[q] = bb[q];
        }
        #pragma unroll 1
        for (int c = 0; c < C1; c++) chan64(act[c], sW1 + c * 64, h);
        #pragma unroll
        for (int q = 0; q < 32; q++) {
            float a, bb2; unpk(h[q], a, bb2);
            act[2 * q] = fmaxf(a, 0.f); act[2 * q + 1] = fmaxf(bb2, 0.f);
        }

        // ---- layer 3: 64 -> 128, then max over K (lanes) ----
        float* outp = out_pts + (size_t)cid * C3;
        #pragma unroll 1
        for (int ch = 0; ch < 2; ch++) {
            ull acc[32];
            #pragma unroll
            for (int q = 0; q < 32; q++) acc[q] = 0ull;
            #pragma unroll 1
            for (int c = 0; c < C2; c++) chan64(act[c], sW2 + c * C3 + ch * 64, acc);
            // butterfly max across lanes (relu & bias commute past max -> after)
            #pragma unroll 1
            for (int off = 16; off; off >>= 1) {
                #pragma unroll
                for (int q = 0; q < 32; q++) {
                    ull o = __shfl_xor_sync(FULL, acc[q], off);
                    float a1, b1v, a2, b2v;
                    unpk(acc[q], a1, b1v); unpk(o, a2, b2v);
                    acc[q] = pk2(fmaxf(a1, a2), fmaxf(b1v, b2v));
                }
            }
            if (lane == 0) {
                #pragma unroll
                for (int q = 0; q < 32; q++) {
                    float a, bb2; unpk(acc[q], a, bb2);
                    float2 v;
                    v.x = fmaxf(a   + sB2[ch * 64 + 2 * q],     0.f);
                    v.y = fmaxf(bb2 + sB2[ch * 64 + 2 * q + 1], 0.f);
                    *(float2*)(outp + ch * 64 + 2 * q) = v;
                }
            }
        }
    }
}

// ---------------- launch ----------------
extern "C" void kernel_launch(void* const* d_in, const int* in_sizes, int n_in,
                              void* d_out, int out_size) {
    const float* xyz    = (const float*)d_in[0];
    const float* points = (const float*)d_in[1];
    float* out = (float*)d_out;
    float* out_nxyz = out;                      // (B,S,3)
    float* out_pts  = out + (size_t)NB * NS * 3; // (B,S,128)

    const int SMEM_FPS  = (3 * NN + 32 + 32 + 3) * 4 + 16;
    const int SMEM_BALL = 3 * NN * 4;
    const int SMEM_MLP  = (C0 * C1 + C1 * C2 + C2 * C3 + C1 + C2 + C3 + 8 * 32 * 65) * 4;

    cudaFuncSetAttribute(k_fps,  cudaFuncAttributeMaxDynamicSharedMemorySize, SMEM_FPS);
    cudaFuncSetAttribute(k_ball, cudaFuncAttributeMaxDynamicSharedMemorySize, SMEM_BALL);
    cudaFuncSetAttribute(k_mlp,  cudaFuncAttributeMaxDynamicSharedMemorySize, SMEM_MLP);

    k_fold<<<64, 256>>>(
        (const float*)d_in[2],  (const float*)d_in[3],  (const float*)d_in[4],
        (const float*)d_in[5],  (const float*)d_in[6],  (const float*)d_in[7],
        (const float*)d_in[8],  (const float*)d_in[9],  (const float*)d_in[10],
        (const float*)d_in[11], (const float*)d_in[12], (const float*)d_in[13],
        (const float*)d_in[14], (const float*)d_in[15], (const float*)d_in[16],
        (const float*)d_in[17], (const float*)d_in[18], (const float*)d_in[19]);

    k_fps <<<NB, 1024, SMEM_FPS>>>(xyz, out_nxyz);
    k_ball<<<NB * 128, 256, SMEM_BALL>>>(xyz, out_nxyz);
    k_mlp <<<1024, 256, SMEM_MLP>>>(xyz, points, out_nxyz, out_pts);
}

// round 5
// speedup vs baseline: 1.5102x; 1.5102x over previous
#include <cuda_runtime.h>
#include <math.h>

#define FULL 0xFFFFFFFFu
typedef unsigned long long ull;

static const int NB = 16, NN = 4096, NS = 1024, NK = 32, ND = 64;
static const int C0 = 67, C1 = 64, C2 = 64, C3 = 128;

// ---------------- scratch (static device globals; no allocs) ----------------
__device__ int   g_ball[NB * NS * NK];          // 2 MB neighbor indices
__device__ float gW0[C0 * C1], gB0[C1];
__device__ float gW1[C1 * C2], gB1[C2];
__device__ float gW2[C2 * C3], gB2[C3];

// exact (non-contracted) squared distance to match reference mul/add semantics
__device__ __forceinline__ float sq3(float ax, float ay, float az,
                                     float bx, float by, float bz) {
    float dx = __fsub_rn(ax, bx), dy = __fsub_rn(ay, by), dz = __fsub_rn(az, bz);
    return __fadd_rn(__fadd_rn(__fmul_rn(dx, dx), __fmul_rn(dy, dy)), __fmul_rn(dz, dz));
}

__device__ __forceinline__ float bn_scale(float g, float v) {
    return (float)((double)g / sqrt((double)v + 1e-5));
}

// ---------------- kernel 0: fold BN into weights ----------------
__global__ void k_fold(const float* W0, const float* b0, const float* g0, const float* be0, const float* m0, const float* v0,
                       const float* W1, const float* b1, const float* g1, const float* be1, const float* m1, const float* v1,
                       const float* W2, const float* b2, const float* g2, const float* be2, const float* m2, const float* v2) {
    int t = blockIdx.x * blockDim.x + threadIdx.x;
    int st = gridDim.x * blockDim.x;
    for (int i = t; i < C0 * C1; i += st) { int j = i % C1; gW0[i] = W0[i] * bn_scale(g0[j], v0[j]); }
    for (int i = t; i < C1 * C2; i += st) { int j = i % C2; gW1[i] = W1[i] * bn_scale(g1[j], v1[j]); }
    for (int i = t; i < C2 * C3; i += st) { int j = i % C3; gW2[i] = W2[i] * bn_scale(g2[j], v2[j]); }
    for (int j = t; j < C1; j += st) gB0[j] = (b0[j] - m0[j]) * bn_scale(g0[j], v0[j]) + be0[j];
    for (int j = t; j < C2; j += st) gB1[j] = (b1[j] - m1[j]) * bn_scale(g1[j], v1[j]) + be1[j];
    for (int j = t; j < C3; j += st) gB2[j] = (b2[j] - m2[j]) * bn_scale(g2[j], v2[j]) + be2[j];
}

// ---------------- kernel 1: farthest point sampling ----------------
// 256 threads, 16 points/thread, ONE barrier per iteration (double-buffered
// partials), redux.sync reductions with exact first-index tie-break.
__global__ void __launch_bounds__(256) k_fps(const float* __restrict__ xyz, float* __restrict__ out) {
    extern __shared__ float sm[];
    float* sx = sm;
    float* sy = sm + NN;
    float* sz = sm + 2 * NN;
    unsigned* rv = (unsigned*)(sz + NN);   // [2][8] value bits
    unsigned* ri = rv + 16;                // [2][8] indices

    int b = blockIdx.x, t = threadIdx.x;
    const float* xb = xyz + (size_t)b * NN * 3;
    for (int j = t; j < NN; j += 256) {
        sx[j] = xb[3 * j]; sy[j] = xb[3 * j + 1]; sz[j] = xb[3 * j + 2];
    }
    __syncthreads();

    float cx = sx[0], cy = sy[0], cz = sz[0];
    if (t == 0) {
        float* o = out + (size_t)b * NS * 3;
        o[0] = cx; o[1] = cy; o[2] = cz;
    }

    float md[16];
    #pragma unroll
    for (int i = 0; i < 16; i++) md[i] = 1e10f;

    int lane = t & 31, w = t >> 5;

    for (int it = 1; it < NS; it++) {
        float bv = -1.0f; int bi = 0;
        #pragma unroll
        for (int i = 0; i < 16; i++) {
            int p = t + (i << 8);
            float d = sq3(sx[p], sy[p], sz[p], cx, cy, cz);
            md[i] = fminf(md[i], d);
            if (md[i] > bv) { bv = md[i]; bi = p; }   // strict > keeps smallest idx
        }
        unsigned vb = __float_as_uint(bv);            // md >= 0 -> order-preserving bits
        unsigned mm = __reduce_max_sync(FULL, vb);
        unsigned cand = (vb == mm) ? (unsigned)bi : 0xFFFFFFFFu;
        cand = __reduce_min_sync(FULL, cand);
        int buf = (it & 1) << 3;
        if (lane == 0) { rv[buf + w] = mm; ri[buf + w] = cand; }
        __syncthreads();
        // every warp redundantly reduces the 8 partials -> no second barrier
        unsigned v8 = (lane < 8) ? rv[buf + lane] : 0u;
        unsigned i8 = (lane < 8) ? ri[buf + lane] : 0xFFFFFFFFu;
        unsigned m2 = __reduce_max_sync(FULL, v8);
        unsigned c2 = (lane < 8 && v8 == m2) ? i8 : 0xFFFFFFFFu;
        c2 = __reduce_min_sync(FULL, c2);
        int nb = (int)c2;
        cx = sx[nb]; cy = sy[nb]; cz = sz[nb];
        if (t == 0) {
            float* o = out + ((size_t)b * NS + it) * 3;
            o[0] = cx; o[1] = cy; o[2] = cz;
        }
    }
}

// ---------------- kernel 2: ball query (first K in index order) ----------------
__global__ void __launch_bounds__(256) k_ball(const float* __restrict__ xyz, const float* __restrict__ nxyz) {
    extern __shared__ float sm[];
    float* sx = sm; float* sy = sm + NN; float* sz = sm + 2 * NN;
    int b  = blockIdx.x >> 7;          // 128 blocks per batch
    int s0 = (blockIdx.x & 127) << 3;  // 8 centroids per block (one per warp)
    const float* xb = xyz + (size_t)b * NN * 3;
    for (int j = threadIdx.x; j < NN; j += 256) {
        sx[j] = xb[3 * j]; sy[j] = xb[3 * j + 1]; sz[j] = xb[3 * j + 2];
    }
    __syncthreads();
    int w = threadIdx.x >> 5, lane = threadIdx.x & 31;
    int s = s0 + w;
    const float* c = nxyz + ((size_t)b * NS + s) * 3;
    float cx = c[0], cy = c[1], cz = c[2];
    const float R2 = (float)(0.2 * 0.2);  // matches python double 0.04 -> f32 cast
    int gb = ((b << 10) + s) * NK;
    int cnt = 0;
    for (int base = 0; base < NN; base += 32) {
        int p = base + lane;
        float d2 = sq3(cx, cy, cz, sx[p], sy[p], sz[p]);
        bool hit = d2 < R2;
        unsigned m = __ballot_sync(FULL, hit);
        int pos = cnt + __popc(m & ((1u << lane) - 1));
        if (hit && pos < NK) g_ball[gb + pos] = p;
        cnt += __popc(m);
        if (cnt >= NK) break;
    }
    int cf = cnt < NK ? cnt : NK;
    if (lane >= cf) g_ball[gb + lane] = -1;
}

// ---------------- packed f32x2 helpers ----------------
__device__ __forceinline__ void ffma2(ull& acc, ull a, ull b) {
    asm("fma.rn.f32x2 %0, %1, %2, %0;" : "+l"(acc) : "l"(a), "l"(b));
}
__device__ __forceinline__ ull bcast2(float x) {
    ull r; asm("mov.b64 %0, {%1, %1};" : "=l"(r) : "f"(x)); return r;
}
__device__ __forceinline__ ull pk2(float a, float b) {
    ull r; asm("mov.b64 %0, {%1, %2};" : "=l"(r) : "f"(a), "f"(b)); return r;
}
__device__ __forceinline__ void unpk(ull v, float& a, float& b) {
    asm("mov.b64 {%0, %1}, %2;" : "=f"(a), "=f"(b) : "l"(v));
}
// dual-centroid: one weight load feeds FOUR ffma2 (2 outputs x 2 centroids)
__device__ __forceinline__ void chan64d(float xa, float xb, const float* wrow,
                                        ull* hA, ull* hB) {
    ull a2 = bcast2(xa), b2 = bcast2(xb);
    const ulonglong2* w2 = (const ulonglong2*)wrow;
    #pragma unroll
    for (int j = 0; j < 16; j++) {
        ulonglong2 w = w2[j];
        ffma2(hA[2 * j],     a2, w.x);
        ffma2(hB[2 * j],     b2, w.x);
        ffma2(hA[2 * j + 1], a2, w.y);
        ffma2(hB[2 * j + 1], b2, w.y);
    }
}

// ---------------- kernel 3: gather + 3-layer MLP + max over K ----------------
// one warp per TWO centroids (weight loads amortized), lane = neighbor k
__global__ void __launch_bounds__(256) k_mlp(const float* __restrict__ xyz,
                                             const float* __restrict__ points,
                                             const float* __restrict__ nxyz,
                                             float* __restrict__ out_pts) {
    extern __shared__ float sm[];
    float* sW0 = sm;                 // 4288
    float* sW1 = sW0 + C0 * C1;      // 4096
    float* sW2 = sW1 + C1 * C2;      // 8192
    float* sB0 = sW2 + C2 * C3;      // 64
    float* sB1 = sB0 + C1;           // 64
    float* sB2 = sB1 + C2;           // 128
    float* sAct = sB2 + C3;          // 16 act-sets * 32 lanes * 65 (padded)

    for (int i = threadIdx.x; i < C0 * C1; i += 256) sW0[i] = gW0[i];
    for (int i = threadIdx.x; i < C1 * C2; i += 256) sW1[i] = gW1[i];
    for (int i = threadIdx.x; i < C2 * C3; i += 256) sW2[i] = gW2[i];
    if (threadIdx.x < C1) sB0[threadIdx.x] = gB0[threadIdx.x];
    if (threadIdx.x < C2) sB1[threadIdx.x] = gB1[threadIdx.x];
    if (threadIdx.x < C3) sB2[threadIdx.x] = gB2[threadIdx.x];
    __syncthreads();

    int w = threadIdx.x >> 5, lane = threadIdx.x & 31;
    float* actA = sAct + (2 * w)     * (32 * 65) + lane * 65;  // conflict-free rows
    float* actB = sAct + (2 * w + 1) * (32 * 65) + lane * 65;

    int cidA = blockIdx.x * 16 + 2 * w;
    int cidB = cidA + 1;
    int bA = cidA >> 10, bB = cidB >> 10;

    const float* cA = nxyz + (size_t)cidA * 3;
    const float* cB = nxyz + (size_t)cidB * 3;
    float cxA = cA[0], cyA = cA[1], czA = cA[2];
    float cxB = cB[0], cyB = cB[1], czB = cB[2];

    int nA = g_ball[cidA * NK + lane];
    int nB = g_ball[cidB * NK + lane];
    int iwA = nA < 0 ? (NN - 1) : nA;   // torch -1 wrap -> N-1
    int iwB = nB < 0 ? (NN - 1) : nB;
    const float4* prA = (const float4*)(points + ((size_t)bA * NN + iwA) * ND);
    const float4* prB = (const float4*)(points + ((size_t)bB * NN + iwB) * ND);

    float x0A, x1A, x2A, x0B, x1B, x2B;
    if (nA >= 0) {
        const float* q = xyz + ((size_t)bA * NN + nA) * 3;
        x0A = __fsub_rn(q[0], cxA); x1A = __fsub_rn(q[1], cyA); x2A = __fsub_rn(q[2], czA);
    } else { x0A = -cxA; x1A = -cyA; x2A = -czA; }  // zeroed before -new_xyz
    if (nB >= 0) {
        const float* q = xyz + ((size_t)bB * NN + nB) * 3;
        x0B = __fsub_rn(q[0], cxB); x1B = __fsub_rn(q[1], cyB); x2B = __fsub_rn(q[2], czB);
    } else { x0B = -cxB; x1B = -cyB; x2B = -czB; }

    ull hA[32], hB[32];

    // ---- layer 1: 67 -> 64 ----
    {
        const ull* bb = (const ull*)sB0;
        #pragma unroll
        for (int q = 0; q < 32; q++) { ull v = bb[q]; hA[q] = v; hB[q] = v; }
    }
    chan64d(x0A, x0B, sW0,       hA, hB);
    chan64d(x1A, x1B, sW0 + 64,  hA, hB);
    chan64d(x2A, x2B, sW0 + 128, hA, hB);
    float4 cA4 = prA[0], cB4 = prB[0];
    #pragma unroll 1
    for (int i = 0; i < 16; i++) {
        float4 nA4 = (i < 15) ? prA[i + 1] : cA4;
        float4 nB4 = (i < 15) ? prB[i + 1] : cB4;
        const float* wr = sW0 + (3 + 4 * i) * 64;
        chan64d(cA4.x, cB4.x, wr,       hA, hB);
        chan64d(cA4.y, cB4.y, wr + 64,  hA, hB);
        chan64d(cA4.z, cB4.z, wr + 128, hA, hB);
        chan64d(cA4.w, cB4.w, wr + 192, hA, hB);
        cA4 = nA4; cB4 = nB4;
    }
    #pragma unroll
    for (int q = 0; q < 32; q++) {
        float a, b2v;
        unpk(hA[q], a, b2v); actA[2 * q] = fmaxf(a, 0.f); actA[2 * q + 1] = fmaxf(b2v, 0.f);
        unpk(hB[q], a, b2v); actB[2 * q] = fmaxf(a, 0.f); actB[2 * q + 1] = fmaxf(b2v, 0.f);
    }

    // ---- layer 2: 64 -> 64 ----
    {
        const ull* bb = (const ull*)sB1;
        #pragma unroll
        for (int q = 0; q < 32; q++) { ull v = bb[q]; hA[q] = v; hB[q] = v; }
    }
    #pragma unroll 1
    for (int c = 0; c < C1; c++) chan64d(actA[c], actB[c], sW1 + c * 64, hA, hB);
    #pragma unroll
    for (int q = 0; q < 32; q++) {
        float a, b2v;
        unpk(hA[q], a, b2v); actA[2 * q] = fmaxf(a, 0.f); actA[2 * q + 1] = fmaxf(b2v, 0.f);
        unpk(hB[q], a, b2v); actB[2 * q] = fmaxf(a, 0.f); actB[2 * q + 1] = fmaxf(b2v, 0.f);
    }

    // ---- layer 3: 64 -> 128, then max over K (lanes) ----
    float* outA = out_pts + (size_t)cidA * C3;
    float* outB = out_pts + (size_t)cidB * C3;
    #pragma unroll 1
    for (int ch = 0; ch < 2; ch++) {
        #pragma unroll
        for (int q = 0; q < 32; q++) { hA[q] = 0ull; hB[q] = 0ull; }
        #pragma unroll 1
        for (int c = 0; c < C2; c++) chan64d(actA[c], actB[c], sW2 + c * C3 + ch * 64, hA, hB);
        // butterfly max across lanes (bias & relu commute past max -> applied after)
        #pragma unroll 1
        for (int off = 16; off; off >>= 1) {
            #pragma unroll
            for (int q = 0; q < 32; q++) {
                ull oA = __shfl_xor_sync(FULL, hA[q], off);
                ull oB = __shfl_xor_sync(FULL, hB[q], off);
                float a1, b1v, a2, b2v;
                unpk(hA[q], a1, b1v); unpk(oA, a2, b2v);
                hA[q] = pk2(fmaxf(a1, a2), fmaxf(b1v, b2v));
                unpk(hB[q], a1, b1v); unpk(oB, a2, b2v);
                hB[q] = pk2(fmaxf(a1, a2), fmaxf(b1v, b2v));
            }
        }
        if (lane == 0) {
            #pragma unroll
            for (int q = 0; q < 32; q++) {
                float a, b2v; unpk(hA[q], a, b2v);
                float2 v;
                v.x = fmaxf(a   + sB2[ch * 64 + 2 * q],     0.f);
                v.y = fmaxf(b2v + sB2[ch * 64 + 2 * q + 1], 0.f);
                *(float2*)(outA + ch * 64 + 2 * q) = v;
            }
        }
        if (lane == 1) {
            #pragma unroll
            for (int q = 0; q < 32; q++) {
                float a, b2v; unpk(hB[q], a, b2v);
                float2 v;
                v.x = fmaxf(a   + sB2[ch * 64 + 2 * q],     0.f);
                v.y = fmaxf(b2v + sB2[ch * 64 + 2 * q + 1], 0.f);
                *(float2*)(outB + ch * 64 + 2 * q) = v;
            }
        }
    }
}

// ---------------- launch ----------------
extern "C" void kernel_launch(void* const* d_in, const int* in_sizes, int n_in,
                              void* d_out, int out_size) {
    const float* xyz    = (const float*)d_in[0];
    const float* points = (const float*)d_in[1];
    float* out = (float*)d_out;
    float* out_nxyz = out;                       // (B,S,3)
    float* out_pts  = out + (size_t)NB * NS * 3; // (B,S,128)

    const int SMEM_FPS  = 3 * NN * 4 + 32 * 4;
    const int SMEM_BALL = 3 * NN * 4;
    const int SMEM_MLP  = (C0 * C1 + C1 * C2 + C2 * C3 + C1 + C2 + C3 + 16 * 32 * 65) * 4;

    cudaFuncSetAttribute(k_fps,  cudaFuncAttributeMaxDynamicSharedMemorySize, SMEM_FPS);
    cudaFuncSetAttribute(k_ball, cudaFuncAttributeMaxDynamicSharedMemorySize, SMEM_BALL);
    cudaFuncSetAttribute(k_mlp,  cudaFuncAttributeMaxDynamicSharedMemorySize, SMEM_MLP);

    k_fold<<<64, 256>>>(
        (const float*)d_in[2],  (const float*)d_in[3],  (const float*)d_in[4],
        (const float*)d_in[5],  (const float*)d_in[6],  (const float*)d_in[7],
        (const float*)d_in[8],  (const float*)d_in[9],  (const float*)d_in[10],
        (const float*)d_in[11], (const float*)d_in[12], (const float*)d_in[13],
        (const float*)d_in[14], (const float*)d_in[15], (const float*)d_in[16],
        (const float*)d_in[17], (const float*)d_in[18], (const float*)d_in[19]);

    k_fps <<<NB, 256, SMEM_FPS>>>(xyz, out_nxyz);
    k_ball<<<NB * 128, 256, SMEM_BALL>>>(xyz, out_nxyz);
    k_mlp <<<1024, 256, SMEM_MLP>>>(xyz, points, out_nxyz, out_pts);
}

// round 6
// speedup vs baseline: 1.6859x; 1.1163x over previous
#include <cuda_runtime.h>
#include <math.h>

#define FULL 0xFFFFFFFFu
typedef unsigned long long ull;

static const int NB = 16, NN = 4096, NS = 1024, NK = 32, ND = 64;
static const int C0 = 67, C1 = 64, C2 = 64, C3 = 128;

// ---------------- scratch (static device globals; no allocs) ----------------
__device__ int   g_ball[NB * NS * NK];          // 2 MB neighbor indices
__device__ float gW0[C0 * C1], gB0[C1];
__device__ float gW1[C1 * C2], gB1[C2];
__device__ float gW2[C2 * C3], gB2[C3];

// exact (non-contracted) squared distance to match reference mul/add semantics
__device__ __forceinline__ float sq3(float ax, float ay, float az,
                                     float bx, float by, float bz) {
    float dx = __fsub_rn(ax, bx), dy = __fsub_rn(ay, by), dz = __fsub_rn(az, bz);
    return __fadd_rn(__fadd_rn(__fmul_rn(dx, dx), __fmul_rn(dy, dy)), __fmul_rn(dz, dz));
}

__device__ __forceinline__ float bn_scale(float g, float v) {
    return (float)((double)g / sqrt((double)v + 1e-5));
}

// ---------------- kernel 0: fold BN into weights ----------------
__global__ void k_fold(const float* W0, const float* b0, const float* g0, const float* be0, const float* m0, const float* v0,
                       const float* W1, const float* b1, const float* g1, const float* be1, const float* m1, const float* v1,
                       const float* W2, const float* b2, const float* g2, const float* be2, const float* m2, const float* v2) {
    int t = blockIdx.x * blockDim.x + threadIdx.x;
    int st = gridDim.x * blockDim.x;
    for (int i = t; i < C0 * C1; i += st) { int j = i % C1; gW0[i] = W0[i] * bn_scale(g0[j], v0[j]); }
    for (int i = t; i < C1 * C2; i += st) { int j = i % C2; gW1[i] = W1[i] * bn_scale(g1[j], v1[j]); }
    for (int i = t; i < C2 * C3; i += st) { int j = i % C3; gW2[i] = W2[i] * bn_scale(g2[j], v2[j]); }
    for (int j = t; j < C1; j += st) gB0[j] = (b0[j] - m0[j]) * bn_scale(g0[j], v0[j]) + be0[j];
    for (int j = t; j < C2; j += st) gB1[j] = (b1[j] - m1[j]) * bn_scale(g1[j], v1[j]) + be1[j];
    for (int j = t; j < C3; j += st) gB2[j] = (b2[j] - m2[j]) * bn_scale(g2[j], v2[j]) + be2[j];
}

// ---------------- kernel 1: farthest point sampling ----------------
// 512 threads, 8 points/thread HELD IN REGISTERS (no LDS in hot loop),
// one barrier per iteration (double-buffered partials), redux.sync argmax
// with exact first-index tie-break.
__global__ void __launch_bounds__(512) k_fps(const float* __restrict__ xyz, float* __restrict__ out) {
    extern __shared__ float sm[];
    float4*   sp = (float4*)sm;            // 4096 float4 (winner lookup only)
    unsigned* rv = (unsigned*)(sp + NN);   // [2][16] value bits
    unsigned* ri = rv + 32;                // [2][16] indices

    int b = blockIdx.x, t = threadIdx.x;
    const float* xb = xyz + (size_t)b * NN * 3;
    float px[8], py[8], pz[8], md[8];
    #pragma unroll
    for (int i = 0; i < 8; i++) {
        int p = t + (i << 9);
        float x = xb[3 * p], y = xb[3 * p + 1], z = xb[3 * p + 2];
        px[i] = x; py[i] = y; pz[i] = z; md[i] = 1e10f;
        sp[p] = make_float4(x, y, z, 0.f);
    }
    __syncthreads();

    float4 c0 = sp[0];
    float cx = c0.x, cy = c0.y, cz = c0.z;
    if (t == 0) {
        float* o = out + (size_t)b * NS * 3;
        o[0] = cx; o[1] = cy; o[2] = cz;
    }

    int lane = t & 31, w = t >> 5;

    for (int it = 1; it < NS; it++) {
        float bv = -1.0f; int bi = 0;
        #pragma unroll
        for (int i = 0; i < 8; i++) {
            float d = sq3(px[i], py[i], pz[i], cx, cy, cz);
            md[i] = fminf(md[i], d);
            if (md[i] > bv) { bv = md[i]; bi = t + (i << 9); }  // strict > keeps smallest idx
        }
        unsigned vb = __float_as_uint(bv);            // md >= 0 -> order-preserving bits
        unsigned mm = __reduce_max_sync(FULL, vb);
        unsigned cand = (vb == mm) ? (unsigned)bi : 0xFFFFFFFFu;
        cand = __reduce_min_sync(FULL, cand);
        int buf = (it & 1) << 4;
        if (lane == 0) { rv[buf + w] = mm; ri[buf + w] = cand; }
        __syncthreads();
        // every warp redundantly reduces the 16 partials -> no second barrier
        unsigned v16 = (lane < 16) ? rv[buf + lane] : 0u;
        unsigned i16 = (lane < 16) ? ri[buf + lane] : 0xFFFFFFFFu;
        unsigned m2 = __reduce_max_sync(FULL, v16);
        unsigned c2 = (lane < 16 && v16 == m2) ? i16 : 0xFFFFFFFFu;
        c2 = __reduce_min_sync(FULL, c2);
        float4 cc = sp[c2];
        cx = cc.x; cy = cc.y; cz = cc.z;
        if (t == 0) {
            float* o = out + ((size_t)b * NS + it) * 3;
            o[0] = cx; o[1] = cy; o[2] = cz;
        }
    }
}

// ---------------- kernel 2: ball query (first K in index order) ----------------
__global__ void __launch_bounds__(256) k_ball(const float* __restrict__ xyz, const float* __restrict__ nxyz) {
    extern __shared__ float sm[];
    float* sx = sm; float* sy = sm + NN; float* sz = sm + 2 * NN;
    int b  = blockIdx.x >> 7;          // 128 blocks per batch
    int s0 = (blockIdx.x & 127) << 3;  // 8 centroids per block (one per warp)
    const float* xb = xyz + (size_t)b * NN * 3;
    for (int j = threadIdx.x; j < NN; j += 256) {
        sx[j] = xb[3 * j]; sy[j] = xb[3 * j + 1]; sz[j] = xb[3 * j + 2];
    }
    __syncthreads();
    int w = threadIdx.x >> 5, lane = threadIdx.x & 31;
    int s = s0 + w;
    const float* c = nxyz + ((size_t)b * NS + s) * 3;
    float cx = c[0], cy = c[1], cz = c[2];
    const float R2 = (float)(0.2 * 0.2);  // matches python double 0.04 -> f32 cast
    int gb = ((b << 10) + s) * NK;
    int cnt = 0;
    for (int base = 0; base < NN; base += 32) {
        int p = base + lane;
        float d2 = sq3(cx, cy, cz, sx[p], sy[p], sz[p]);
        bool hit = d2 < R2;
        unsigned m = __ballot_sync(FULL, hit);
        int pos = cnt + __popc(m & ((1u << lane) - 1));
        if (hit && pos < NK) g_ball[gb + pos] = p;
        cnt += __popc(m);
        if (cnt >= NK) break;
    }
    int cf = cnt < NK ? cnt : NK;
    if (lane >= cf) g_ball[gb + lane] = -1;
}

// ---------------- packed f32x2 helpers ----------------
__device__ __forceinline__ void ffma2(ull& acc, ull a, ull b) {
    asm("fma.rn.f32x2 %0, %1, %2, %0;" : "+l"(acc) : "l"(a), "l"(b));
}
__device__ __forceinline__ ull bcast2(float x) {
    ull r; asm("mov.b64 %0, {%1, %1};" : "=l"(r) : "f"(x)); return r;
}
__device__ __forceinline__ ull pk2(float a, float b) {
    ull r; asm("mov.b64 %0, {%1, %2};" : "=l"(r) : "f"(a), "f"(b)); return r;
}
__device__ __forceinline__ void unpk(ull v, float& a, float& b) {
    asm("mov.b64 {%0, %1}, %2;" : "=f"(a), "=f"(b) : "l"(v));
}
// dual-centroid: one weight load feeds FOUR ffma2 (2 outputs x 2 centroids)
__device__ __forceinline__ void chan64d(float xa, float xb, const float* wrow,
                                        ull* hA, ull* hB) {
    ull a2 = bcast2(xa), b2 = bcast2(xb);
    const ulonglong2* w2 = (const ulonglong2*)wrow;
    #pragma unroll
    for (int j = 0; j < 16; j++) {
        ulonglong2 w = w2[j];
        ffma2(hA[2 * j],     a2, w.x);
        ffma2(hB[2 * j],     b2, w.x);
        ffma2(hA[2 * j + 1], a2, w.y);
        ffma2(hB[2 * j + 1], b2, w.y);
    }
}

// ---------------- kernel 3: gather + 3-layer MLP + max over K ----------------
// one warp per TWO centroids (weight loads amortized), lane = neighbor k
__global__ void __launch_bounds__(256) k_mlp(const float* __restrict__ xyz,
                                             const float* __restrict__ points,
                                             const float* __restrict__ nxyz,
                                             float* __restrict__ out_pts) {
    extern __shared__ float sm[];
    float* sW0 = sm;                 // 4288
    float* sW1 = sW0 + C0 * C1;      // 4096
    float* sW2 = sW1 + C1 * C2;      // 8192
    float* sB0 = sW2 + C2 * C3;      // 64
    float* sB1 = sB0 + C1;           // 64
    float* sB2 = sB1 + C2;           // 128
    float* sAct = sB2 + C3;          // 16 act-sets * 32 lanes * 65 (padded)

    for (int i = threadIdx.x; i < C0 * C1; i += 256) sW0[i] = gW0[i];
    for (int i = threadIdx.x; i < C1 * C2; i += 256) sW1[i] = gW1[i];
    for (int i = threadIdx.x; i < C2 * C3; i += 256) sW2[i] = gW2[i];
    if (threadIdx.x < C1) sB0[threadIdx.x] = gB0[threadIdx.x];
    if (threadIdx.x < C2) sB1[threadIdx.x] = gB1[threadIdx.x];
    if (threadIdx.x < C3) sB2[threadIdx.x] = gB2[threadIdx.x];
    __syncthreads();

    int w = threadIdx.x >> 5, lane = threadIdx.x & 31;
    float* actA = sAct + (2 * w)     * (32 * 65) + lane * 65;  // conflict-free rows
    float* actB = sAct + (2 * w + 1) * (32 * 65) + lane * 65;

    int cidA = blockIdx.x * 16 + 2 * w;
    int cidB = cidA + 1;
    int bA = cidA >> 10, bB = cidB >> 10;

    const float* cA = nxyz + (size_t)cidA * 3;
    const float* cB = nxyz + (size_t)cidB * 3;
    float cxA = cA[0], cyA = cA[1], czA = cA[2];
    float cxB = cB[0], cyB = cB[1], czB = cB[2];

    int nA = g_ball[cidA * NK + lane];
    int nB = g_ball[cidB * NK + lane];
    int iwA = nA < 0 ? (NN - 1) : nA;   // torch -1 wrap -> N-1
    int iwB = nB < 0 ? (NN - 1) : nB;
    const float4* prA = (const float4*)(points + ((size_t)bA * NN + iwA) * ND);
    const float4* prB = (const float4*)(points + ((size_t)bB * NN + iwB) * ND);

    float x0A, x1A, x2A, x0B, x1B, x2B;
    if (nA >= 0) {
        const float* q = xyz + ((size_t)bA * NN + nA) * 3;
        x0A = __fsub_rn(q[0], cxA); x1A = __fsub_rn(q[1], cyA); x2A = __fsub_rn(q[2], czA);
    } else { x0A = -cxA; x1A = -cyA; x2A = -czA; }  // zeroed before -new_xyz
    if (nB >= 0) {
        const float* q = xyz + ((size_t)bB * NN + nB) * 3;
        x0B = __fsub_rn(q[0], cxB); x1B = __fsub_rn(q[1], cyB); x2B = __fsub_rn(q[2], czB);
    } else { x0B = -cxB; x1B = -cyB; x2B = -czB; }

    ull hA[32], hB[32];

    // ---- layer 1: 67 -> 64 ----
    {
        const ull* bb = (const ull*)sB0;
        #pragma unroll
        for (int q = 0; q < 32; q++) { ull v = bb[q]; hA[q] = v; hB[q] = v; }
    }
    chan64d(x0A, x0B, sW0,       hA, hB);
    chan64d(x1A, x1B, sW0 + 64,  hA, hB);
    chan64d(x2A, x2B, sW0 + 128, hA, hB);
    float4 cA4 = prA[0], cB4 = prB[0];
    #pragma unroll 1
    for (int i = 0; i < 16; i++) {
        float4 nA4 = (i < 15) ? prA[i + 1] : cA4;
        float4 nB4 = (i < 15) ? prB[i + 1] : cB4;
        const float* wr = sW0 + (3 + 4 * i) * 64;
        chan64d(cA4.x, cB4.x, wr,       hA, hB);
        chan64d(cA4.y, cB4.y, wr + 64,  hA, hB);
        chan64d(cA4.z, cB4.z, wr + 128, hA, hB);
        chan64d(cA4.w, cB4.w, wr + 192, hA, hB);
        cA4 = nA4; cB4 = nB4;
    }
    #pragma unroll
    for (int q = 0; q < 32; q++) {
        float a, b2v;
        unpk(hA[q], a, b2v); actA[2 * q] = fmaxf(a, 0.f); actA[2 * q + 1] = fmaxf(b2v, 0.f);
        unpk(hB[q], a, b2v); actB[2 * q] = fmaxf(a, 0.f); actB[2 * q + 1] = fmaxf(b2v, 0.f);
    }

    // ---- layer 2: 64 -> 64 (with act prefetch) ----
    {
        const ull* bb = (const ull*)sB1;
        #pragma unroll
        for (int q = 0; q < 32; q++) { ull v = bb[q]; hA[q] = v; hB[q] = v; }
    }
    {
        float aA = actA[0], aB = actB[0];
        #pragma unroll 1
        for (int c = 0; c < C1; c++) {
            float nxA = actA[c + 1], nxB = actB[c + 1];  // c=63 hits pad slot (in-bounds)
            chan64d(aA, aB, sW1 + c * 64, hA, hB);
            aA = nxA; aB = nxB;
        }
    }
    #pragma unroll
    for (int q = 0; q < 32; q++) {
        float a, b2v;
        unpk(hA[q], a, b2v); actA[2 * q] = fmaxf(a, 0.f); actA[2 * q + 1] = fmaxf(b2v, 0.f);
        unpk(hB[q], a, b2v); actB[2 * q] = fmaxf(a, 0.f); actB[2 * q + 1] = fmaxf(b2v, 0.f);
    }

    // ---- layer 3: 64 -> 128, then max over K via recursive halving ----
    float* outA = out_pts + (size_t)cidA * C3;
    float* outB = out_pts + (size_t)cidB * C3;
    #pragma unroll 1
    for (int ch = 0; ch < 2; ch++) {
        #pragma unroll
        for (int q = 0; q < 32; q++) { hA[q] = 0ull; hB[q] = 0ull; }
        {
            float aA = actA[0], aB = actB[0];
            #pragma unroll 1
            for (int c = 0; c < C2; c++) {
                float nxA = actA[c + 1], nxB = actB[c + 1];
                chan64d(aA, aB, sW2 + c * C3 + ch * 64, hA, hB);
                aA = nxA; aB = nxB;
            }
        }
        // recursive-halving allreduce-scatter max across lanes:
        // after all steps, lane l holds fully-reduced channel pair q=l.
        #pragma unroll
        for (int m = 16; m >= 1; m >>= 1) {
            bool hi = (lane & m) != 0;
            #pragma unroll
            for (int i = 0; i < m; i++) {
                ull keepA = hi ? hA[i + m] : hA[i];
                ull sendA = hi ? hA[i]     : hA[i + m];
                ull othA  = __shfl_xor_sync(FULL, sendA, m);
                float a1, b1v, a2, b2v;
                unpk(keepA, a1, b1v); unpk(othA, a2, b2v);
                hA[i] = pk2(fmaxf(a1, a2), fmaxf(b1v, b2v));
                ull keepB = hi ? hB[i + m] : hB[i];
                ull sendB = hi ? hB[i]     : hB[i + m];
                ull othB  = __shfl_xor_sync(FULL, sendB, m);
                unpk(keepB, a1, b1v); unpk(othB, a2, b2v);
                hB[i] = pk2(fmaxf(a1, a2), fmaxf(b1v, b2v));
            }
        }
        // bias + relu commute past max; lane l -> channels {2l, 2l+1}; coalesced STG.64
        float bx = sB2[ch * 64 + 2 * lane];
        float by = sB2[ch * 64 + 2 * lane + 1];
        float a1, b1v;
        unpk(hA[0], a1, b1v);
        float2 vA; vA.x = fmaxf(a1 + bx, 0.f); vA.y = fmaxf(b1v + by, 0.f);
        *(float2*)(outA + ch * 64 + 2 * lane) = vA;
        unpk(hB[0], a1, b1v);
        float2 vB; vB.x = fmaxf(a1 + bx, 0.f); vB.y = fmaxf(b1v + by, 0.f);
        *(float2*)(outB + ch * 64 + 2 * lane) = vB;
    }
}

// ---------------- launch ----------------
extern "C" void kernel_launch(void* const* d_in, const int* in_sizes, int n_in,
                              void* d_out, int out_size) {
    const float* xyz    = (const float*)d_in[0];
    const float* points = (const float*)d_in[1];
    float* out = (float*)d_out;
    float* out_nxyz = out;                       // (B,S,3)
    float* out_pts  = out + (size_t)NB * NS * 3; // (B,S,128)

    const int SMEM_FPS  = NN * 16 + 64 * 4;
    const int SMEM_BALL = 3 * NN * 4;
    const int SMEM_MLP  = (C0 * C1 + C1 * C2 + C2 * C3 + C1 + C2 + C3 + 16 * 32 * 65) * 4;

    cudaFuncSetAttribute(k_fps,  cudaFuncAttributeMaxDynamicSharedMemorySize, SMEM_FPS);
    cudaFuncSetAttribute(k_ball, cudaFuncAttributeMaxDynamicSharedMemorySize, SMEM_BALL);
    cudaFuncSetAttribute(k_mlp,  cudaFuncAttributeMaxDynamicSharedMemorySize, SMEM_MLP);

    k_fold<<<64, 256>>>(
        (const float*)d_in[2],  (const float*)d_in[3],  (const float*)d_in[4],
        (const float*)d_in[5],  (const float*)d_in[6],  (const float*)d_in[7],
        (const float*)d_in[8],  (const float*)d_in[9],  (const float*)d_in[10],
        (const float*)d_in[11], (const float*)d_in[12], (const float*)d_in[13],
        (const float*)d_in[14], (const float*)d_in[15], (const float*)d_in[16],
        (const float*)d_in[17], (const float*)d_in[18], (const float*)d_in[19]);

    k_fps <<<NB, 512, SMEM_FPS>>>(xyz, out_nxyz);
    k_ball<<<NB * 128, 256, SMEM_BALL>>>(xyz, out_nxyz);
    k_mlp <<<1024, 256, SMEM_MLP>>>(xyz, points, out_nxyz, out_pts);
}